// round 2
// baseline (speedup 1.0000x reference)
#include <cuda_runtime.h>
#include <math.h>

#define Nn 20000
#define Ee 320000
#define Hh 128
#define Kk 4
#define Ll 3
#define Bb 64
#define Cc 2

// output layout (flattened tuple, row-major each)
#define OUT_LOGITS 0        // [B,K,C]   512
#define OUT_HSTAB  512      // [B,K,H]   32768
#define OUT_HORIG  33280    // [B,H]     8192
#define OUT_NM     41472    // [N,K,1]   80000
#define OUT_EM     121472   // [E,K,1]   1280000

// ---------------- scratch (static device arrays; no runtime alloc) ----------------
__device__ float g_h0[Nn * Hh];
__device__ float g_h1[Nn * Hh];
__device__ float g_z [Nn * Hh];
__device__ float g_P [(size_t)Nn * Kk * 2 * Hh];     // [N][8][128]: (k,top/bot) blocks
__device__ float g_eh0[(size_t)Kk * Nn * Hh];
__device__ float g_eh1[(size_t)Kk * Nn * Hh];
__device__ float g_ez [(size_t)Kk * Nn * Hh];
__device__ float g_emT[(size_t)Kk * Ee];             // transposed edge masks for agg
__device__ int   g_deg[Nn];
__device__ int   g_off[Nn + 1];
__device__ int   g_cur[Nn];
__device__ int   g_csr_src[Ee];
__device__ int   g_csr_eid[Ee];
__device__ int   g_nwflag[Kk * Nn];
__device__ int   g_bstart[Bb + 1];

// ---------------- f32x2 helpers ----------------
__device__ __forceinline__ void ffma2(unsigned long long& d, unsigned long long a, unsigned long long b) {
    asm("fma.rn.f32x2 %0, %1, %2, %0;" : "+l"(d) : "l"(a), "l"(b));
}
__device__ __forceinline__ unsigned long long pk2(float lo) {
    unsigned long long r;
    asm("mov.b64 %0, {%1, %2};" : "=l"(r) : "f"(lo), "f"(0.0f));
    return r;
}
__device__ __forceinline__ float2 unpk2(unsigned long long v) {
    float2 r;
    asm("mov.b64 {%0, %1}, %2;" : "=f"(r.x), "=f"(r.y) : "l"(v));
    return r;
}

// interleave weights into k-pair layout: wp[(k/2)*256 + c*2 + (k&1)] = W[k*128+c]
__device__ __forceinline__ void load_w_pairs(float* wp, const float* __restrict__ W, int tid) {
    for (int i = tid * 4; i < 16384; i += 1024) {
        float4 a = *(const float4*)&W[i];
        int k = i >> 7, c = i & 127;
        int base = (k >> 1) * 256 + c * 2 + (k & 1);
        wp[base] = a.x; wp[base + 2] = a.y; wp[base + 4] = a.z; wp[base + 6] = a.w;
    }
}

// one 64x128 @ 128x128 pass with packed f32x2 FFMA; rows r0..r0+7 (warp-private), cols c0..c0+3
__device__ __forceinline__ void gemm_pass(const float* __restrict__ wp, const float* __restrict__ ts,
                                          float b0, float b1v, float b2v, float b3v,
                                          int r0, int c0, float4 out[8]) {
    unsigned long long acc[8][4];
    unsigned long long ib0 = pk2(b0), ib1 = pk2(b1v), ib2 = pk2(b2v), ib3 = pk2(b3v);
#pragma unroll
    for (int i = 0; i < 8; i++) { acc[i][0] = ib0; acc[i][1] = ib1; acc[i][2] = ib2; acc[i][3] = ib3; }
#pragma unroll 4
    for (int k2 = 0; k2 < 64; k2++) {
        ulonglong2 wA = *(const ulonglong2*)&wp[k2 * 256 + c0 * 2];
        ulonglong2 wB = *(const ulonglong2*)&wp[k2 * 256 + c0 * 2 + 4];
#pragma unroll
        for (int i = 0; i < 8; i++) {
            unsigned long long z2 = *(const unsigned long long*)&ts[(r0 + i) * 128 + 2 * k2];
            ffma2(acc[i][0], z2, wA.x);
            ffma2(acc[i][1], z2, wA.y);
            ffma2(acc[i][2], z2, wB.x);
            ffma2(acc[i][3], z2, wB.y);
        }
    }
#pragma unroll
    for (int i = 0; i < 8; i++) {
        float2 a0 = unpk2(acc[i][0]), a1 = unpk2(acc[i][1]);
        float2 a2 = unpk2(acc[i][2]), a3 = unpk2(acc[i][3]);
        out[i] = make_float4(a0.x + a0.y, a1.x + a1.y, a2.x + a2.y, a3.x + a3.y);
    }
}

// ---------------- CSR build ----------------
__global__ void zero_prep() {
    int i = blockIdx.x * blockDim.x + threadIdx.x;
    if (i < Nn) g_deg[i] = 0;
    if (i < Kk * Nn) g_nwflag[i] = 0;
}

__global__ void hist_deg(const int* __restrict__ ei) {
    int e = blockIdx.x * blockDim.x + threadIdx.x;
    if (e < Ee) atomicAdd(&g_deg[ei[Ee + e]], 1);
}

__global__ void scan_kernel() {
    __shared__ int sh[1024];
    __shared__ int carry;
    int tid = threadIdx.x;
    if (tid == 0) carry = 0;
    __syncthreads();
    for (int base = 0; base < Nn; base += 1024) {
        int i = base + tid;
        int v = (i < Nn) ? g_deg[i] : 0;
        sh[tid] = v;
        __syncthreads();
        for (int ofs = 1; ofs < 1024; ofs <<= 1) {
            int t = (tid >= ofs) ? sh[tid - ofs] : 0;
            __syncthreads();
            sh[tid] += t;
            __syncthreads();
        }
        int incl = sh[tid];
        int excl = incl - v;
        int c = carry;
        if (i < Nn) { g_off[i] = c + excl; g_cur[i] = c + excl; }
        __syncthreads();
        if (tid == 1023) carry = c + incl;
        __syncthreads();
    }
    if (tid == 0) g_off[Nn] = carry;
}

__global__ void csr_fill(const int* __restrict__ ei) {
    int e = blockIdx.x * blockDim.x + threadIdx.x;
    if (e < Ee) {
        int d = ei[Ee + e];
        int p = atomicAdd(&g_cur[d], 1);
        g_csr_src[p] = ei[e];
        g_csr_eid[p] = e;
    }
}

__global__ void bstart_kernel(const int* __restrict__ batch) {
    int n = blockIdx.x * blockDim.x + threadIdx.x;
    if (n >= Nn) return;
    int bn = batch[n];
    if (n == 0) { for (int b = 0; b <= bn; b++) g_bstart[b] = 0; }
    else {
        int bp = batch[n - 1];
        for (int b = bp + 1; b <= bn; b++) g_bstart[b] = n;
    }
    if (n == Nn - 1) { for (int b = bn + 1; b <= Bb; b++) g_bstart[b] = Nn; }
}

// ---------------- aggregation (warp per node, CSR by dst) ----------------
__global__ void agg_enc(const float* __restrict__ hin, const float* __restrict__ epsp) {
    int w = (blockIdx.x * blockDim.x + threadIdx.x) >> 5;
    if (w >= Nn) return;
    int lane = threadIdx.x & 31;
    int col = lane * 4;
    int s = g_off[w], e = g_off[w + 1];
    float4 acc = make_float4(0.f, 0.f, 0.f, 0.f);
    for (int j = s; j < e; j++) {
        int sn = __ldg(&g_csr_src[j]);
        float4 v = *(const float4*)&hin[(size_t)sn * Hh + col];
        acc.x += v.x; acc.y += v.y; acc.z += v.z; acc.w += v.w;
    }
    float ep = 1.0f + __ldg(epsp);
    float4 hv = *(const float4*)&hin[(size_t)w * Hh + col];
    float4 z;
    z.x = fmaf(ep, hv.x, acc.x); z.y = fmaf(ep, hv.y, acc.y);
    z.z = fmaf(ep, hv.z, acc.z); z.w = fmaf(ep, hv.w, acc.w);
    *(float4*)&g_z[(size_t)w * Hh + col] = z;
}

__global__ void agg_exp(const float* __restrict__ hin, const float* __restrict__ epsp) {
    int k = blockIdx.z;
    int w = (blockIdx.x * blockDim.x + threadIdx.x) >> 5;
    if (w >= Nn) return;
    int lane = threadIdx.x & 31;
    int col = lane * 4;
    int s = g_off[w], e = g_off[w + 1];
    const float* hk = hin + (size_t)k * Nn * Hh;
    const float* emk = g_emT + (size_t)k * Ee;
    float4 acc = make_float4(0.f, 0.f, 0.f, 0.f);
    for (int j = s; j < e; j++) {
        int sn = __ldg(&g_csr_src[j]);
        int eid = __ldg(&g_csr_eid[j]);
        float wt = __ldg(&emk[eid]);
        if (wt != 0.0f) {
            float4 v = *(const float4*)&hk[(size_t)sn * Hh + col];
            acc.x = fmaf(wt, v.x, acc.x); acc.y = fmaf(wt, v.y, acc.y);
            acc.z = fmaf(wt, v.z, acc.z); acc.w = fmaf(wt, v.w, acc.w);
        }
    }
    float ep = 1.0f + __ldg(&epsp[k * Ll]);
    float4 hv = *(const float4*)&hk[(size_t)w * Hh + col];
    float4 z;
    z.x = fmaf(ep, hv.x, acc.x); z.y = fmaf(ep, hv.y, acc.y);
    z.z = fmaf(ep, hv.z, acc.z); z.w = fmaf(ep, hv.w, acc.w);
    *(float4*)&g_ez[((size_t)k * Nn + w) * Hh + col] = z;
}

// ---------------- fused 2-layer MLP: h = relu(relu(z@W1+b1)@W2+b2) ----------------
// block 256 threads, TM=64 rows, W1+W2 (pair-interleaved) + tile in dynamic smem (163840 B)
__global__ void __launch_bounds__(256, 1)
mlp2_kernel(const float* __restrict__ zin, float* __restrict__ hout,
            const float* __restrict__ W1, const float* __restrict__ b1,
            const float* __restrict__ W2, const float* __restrict__ b2,
            int M, int wstride, int bstride) {
    extern __shared__ float sm[];
    float* w1s = sm;          // 16384
    float* w2s = sm + 16384;  // 16384
    float* ts  = sm + 32768;  // 64*128 = 8192
    int k = blockIdx.z;
    const float* W1k = W1 + (size_t)k * wstride;
    const float* W2k = W2 + (size_t)k * wstride;
    const float* b1k = b1 + (size_t)k * bstride;
    const float* b2k = b2 + (size_t)k * bstride;
    const float* zk  = zin  + (size_t)k * M * Hh;
    float*       hk  = hout + (size_t)k * M * Hh;
    int tid = threadIdx.x;

    load_w_pairs(w1s, W1k, tid);
    load_w_pairs(w2s, W2k, tid);
    int row0 = blockIdx.x * 64;
    for (int i = tid * 4; i < 8192; i += 1024) {
        int r = i >> 7, c = i & 127;
        int gr = row0 + r;
        float4 v = make_float4(0.f, 0.f, 0.f, 0.f);
        if (gr < M) v = *(const float4*)&zk[(size_t)gr * Hh + c];
        *(float4*)&ts[i] = v;
    }
    __syncthreads();

    int wr = tid >> 5, lane = tid & 31;
    int r0 = wr * 8, c0 = lane * 4;
    float4 out[8];
    gemm_pass(w1s, ts, b1k[c0], b1k[c0 + 1], b1k[c0 + 2], b1k[c0 + 3], r0, c0, out);
    // rows r0..r0+7 are private to this warp: only warp-level sync needed
    __syncwarp();
#pragma unroll
    for (int i = 0; i < 8; i++) {
        float4 h;
        h.x = fmaxf(out[i].x, 0.f); h.y = fmaxf(out[i].y, 0.f);
        h.z = fmaxf(out[i].z, 0.f); h.w = fmaxf(out[i].w, 0.f);
        *(float4*)&ts[(r0 + i) * 128 + c0] = h;
    }
    __syncwarp();
    gemm_pass(w2s, ts, b2k[c0], b2k[c0 + 1], b2k[c0 + 2], b2k[c0 + 3], r0, c0, out);
#pragma unroll
    for (int i = 0; i < 8; i++) {
        int gr = row0 + r0 + i;
        if (gr < M) {
            float4 h;
            h.x = fmaxf(out[i].x, 0.f); h.y = fmaxf(out[i].y, 0.f);
            h.z = fmaxf(out[i].z, 0.f); h.w = fmaxf(out[i].w, 0.f);
            *(float4*)&hk[(size_t)gr * Hh + c0] = h;
        }
    }
}

// ---------------- single-layer GEMM: P[:, ct*128:(ct+1)*128] = Z @ Wct (+ bias for top) ----------------
__global__ void __launch_bounds__(256, 1)
gemm1_kernel(const float* __restrict__ zin, const float* __restrict__ mW1,
             const float* __restrict__ mb1, int M) {
    extern __shared__ float sm[];
    float* ws = sm;           // 16384
    float* ts = sm + 16384;   // 8192
    int ct = blockIdx.y;      // 0..7 : ct = 2*k + half
    int kq = ct >> 1, half = ct & 1;
    const float* Wt = mW1 + (size_t)ct * 16384;
    int tid = threadIdx.x;
    load_w_pairs(ws, Wt, tid);
    int row0 = blockIdx.x * 64;
    for (int i = tid * 4; i < 8192; i += 1024) {
        int r = i >> 7, c = i & 127;
        int gr = row0 + r;
        float4 v = make_float4(0.f, 0.f, 0.f, 0.f);
        if (gr < M) v = *(const float4*)&zin[(size_t)gr * Hh + c];
        *(float4*)&ts[i] = v;
    }
    __syncthreads();
    int wr = tid >> 5, lane = tid & 31;
    int r0 = wr * 8, c0 = lane * 4;
    float bx = 0.f, by = 0.f, bz = 0.f, bw = 0.f;
    if (half == 0) {
        bx = mb1[kq * 128 + c0];     by = mb1[kq * 128 + c0 + 1];
        bz = mb1[kq * 128 + c0 + 2]; bw = mb1[kq * 128 + c0 + 3];
    }
    float4 out[8];
    gemm_pass(ws, ts, bx, by, bz, bw, r0, c0, out);
#pragma unroll
    for (int i = 0; i < 8; i++) {
        int gr = row0 + r0 + i;
        if (gr < M)
            *(float4*)&g_P[(size_t)gr * 1024 + ct * 128 + c0] = out[i];
    }
}

// ---------------- edge masks (warp per edge, all K experts) ----------------
__global__ void edge_mask_kernel(const int* __restrict__ ei, const float* __restrict__ u,
                                 const float* __restrict__ mW2, const float* __restrict__ mb2,
                                 float* __restrict__ dout) {
    __shared__ float w2s[Kk * Hh];
    int tid = threadIdx.x;
    for (int i = tid; i < Kk * Hh; i += blockDim.x) w2s[i] = mW2[i];
    __syncthreads();
    int wid = tid >> 5, lane = tid & 31;
    int e = blockIdx.x * 8 + wid;
    if (e >= Ee) return;
    int src = ei[e], dst = ei[Ee + e];
    const float* Ps = g_P + (size_t)src * 1024;
    const float* Pd = g_P + (size_t)dst * 1024 + 128;
    float r[4];
#pragma unroll
    for (int k = 0; k < 4; k++) {
        float4 pt = *(const float4*)&Ps[k * 256 + lane * 4];
        float4 pb = *(const float4*)&Pd[k * 256 + lane * 4];
        float4 wv = *(const float4*)&w2s[k * 128 + lane * 4];
        float a = fmaxf(pt.x + pb.x, 0.f) * wv.x + fmaxf(pt.y + pb.y, 0.f) * wv.y
                + fmaxf(pt.z + pb.z, 0.f) * wv.z + fmaxf(pt.w + pb.w, 0.f) * wv.w;
#pragma unroll
        for (int o = 16; o > 0; o >>= 1) a += __shfl_xor_sync(0xffffffffu, a, o);
        r[k] = a;
    }
    if (lane < 4) {
        int k = lane;
        float em = r[k] + mb2[k];
        float uu = u[(size_t)e * Kk + k];
        float gmb = -logf(-logf(uu + 1e-20f) + 1e-20f);
        float t = (em + gmb) / 0.1f;
        float ys = 1.0f / (1.0f + expf(-t));
        float yh = (ys > 0.5f) ? 1.0f : 0.0f;
        float eo = (yh + ys) - ys;
        dout[OUT_EM + (size_t)e * Kk + k] = eo;
        g_emT[(size_t)k * Ee + e] = eo;
        if (eo > 0.0f) {
            g_nwflag[k * Nn + src] = 1;
            g_nwflag[k * Nn + dst] = 1;
        }
    }
}

__global__ void nodemask_kernel(float* __restrict__ dout) {
    int n = blockIdx.x * blockDim.x + threadIdx.x;
    if (n >= Nn) return;
    float4 v;
    v.x = g_nwflag[0 * Nn + n] ? 1.f : 0.f;
    v.y = g_nwflag[1 * Nn + n] ? 1.f : 0.f;
    v.z = g_nwflag[2 * Nn + n] ? 1.f : 0.f;
    v.w = g_nwflag[3 * Nn + n] ? 1.f : 0.f;
    *(float4*)&dout[OUT_NM + (size_t)n * 4] = v;
}

__global__ void maskedx_kernel(const float* __restrict__ x) {
    size_t i = (size_t)blockIdx.x * blockDim.x + threadIdx.x;
    if (i >= (size_t)Kk * Nn * 32) return;
    size_t kn = i >> 5;
    int col = (int)(i & 31) * 4;
    size_t n = kn % Nn;
    float4 xv = *(const float4*)&x[n * Hh + col];
    if (!g_nwflag[kn]) xv = make_float4(0.f, 0.f, 0.f, 0.f);
    *(float4*)&g_eh0[kn * Hh + col] = xv;
}

// ---------------- pooling + head ----------------
__global__ void pool_kernel(float* __restrict__ dout) {
    int b = blockIdx.x, which = blockIdx.y;
    int part = threadIdx.x >> 7;       // 0..3
    int f = threadIdx.x & 127;
    __shared__ float red[4][128];
    int s = g_bstart[b], e = g_bstart[b + 1];
    int cnt = e - s;
    const float* src;
    float* dp;
    if (which == Kk) { src = g_h0; dp = dout + OUT_HORIG + (size_t)b * Hh; }
    else {
        src = g_eh1 + (size_t)which * Nn * Hh;
        dp = dout + OUT_HSTAB + (size_t)b * (Kk * Hh) + which * Hh;
    }
    int chunk = (cnt + 3) >> 2;
    int ps = s + part * chunk;
    int pe = ps + chunk; if (pe > e) pe = e;
    float acc = 0.f;
    for (int n = ps; n < pe; n++) acc += src[(size_t)n * Hh + f];
    red[part][f] = acc;
    __syncthreads();
    if (part == 0) {
        float v = red[0][f] + red[1][f] + red[2][f] + red[3][f];
        dp[f] = v / fmaxf((float)cnt, 1.0f);
    }
}

__global__ void head_kernel(const float* __restrict__ hW1, const float* __restrict__ hb1,
                            const float* __restrict__ hW2, const float* __restrict__ hb2,
                            float* __restrict__ dout) {
    int k = blockIdx.x, f = threadIdx.x;
    __shared__ float hid[Bb][Hh];
    const float* hs = dout + OUT_HSTAB;
    const float* W1 = hW1 + (size_t)k * Hh * Hh;
    for (int b = 0; b < Bb; b++) {
        float acc = hb1[k * Hh + f];
        for (int i = 0; i < Hh; i++)
            acc = fmaf(hs[(size_t)b * (Kk * Hh) + k * Hh + i], W1[i * Hh + f], acc);
        hid[b][f] = fmaxf(acc, 0.f);
    }
    __syncthreads();
    int b = f >> 1, c = f & 1;
    const float* W2 = hW2 + (size_t)k * Hh * Cc;
    float acc = hb2[k * Cc + c];
    for (int i = 0; i < Hh; i++)
        acc = fmaf(hid[b][i], W2[i * Cc + c], acc);
    dout[OUT_LOGITS + (size_t)b * (Kk * Cc) + k * Cc + c] = acc;
}

// ---------------- launch ----------------
extern "C" void kernel_launch(void* const* d_in, const int* in_sizes, int n_in,
                              void* d_out, int out_size) {
    const float* x       = (const float*)d_in[0];
    const int*   ei      = (const int*)d_in[1];
    const int*   batch   = (const int*)d_in[2];
    const float* u       = (const float*)d_in[3];
    const float* enc_W1  = (const float*)d_in[4];
    const float* enc_b1  = (const float*)d_in[5];
    const float* enc_W2  = (const float*)d_in[6];
    const float* enc_b2  = (const float*)d_in[7];
    const float* enc_eps = (const float*)d_in[8];
    const float* cls_W1  = (const float*)d_in[9];
    const float* cls_b1  = (const float*)d_in[10];
    const float* cls_W2  = (const float*)d_in[11];
    const float* cls_b2  = (const float*)d_in[12];
    const float* cls_eps = (const float*)d_in[13];
    const float* mask_W1 = (const float*)d_in[14];
    const float* mask_b1 = (const float*)d_in[15];
    const float* mask_W2 = (const float*)d_in[16];
    const float* mask_b2 = (const float*)d_in[17];
    const float* head_W1 = (const float*)d_in[18];
    const float* head_b1 = (const float*)d_in[19];
    const float* head_W2 = (const float*)d_in[20];
    const float* head_b2 = (const float*)d_in[21];
    float* out = (float*)d_out;

    cudaFuncSetAttribute(mlp2_kernel, cudaFuncAttributeMaxDynamicSharedMemorySize, 163840);
    cudaFuncSetAttribute(gemm1_kernel, cudaFuncAttributeMaxDynamicSharedMemorySize, 98304);

    float *ph0, *ph1, *pz, *peh0, *peh1, *pez;
    cudaGetSymbolAddress((void**)&ph0, g_h0);
    cudaGetSymbolAddress((void**)&ph1, g_h1);
    cudaGetSymbolAddress((void**)&pz, g_z);
    cudaGetSymbolAddress((void**)&peh0, g_eh0);
    cudaGetSymbolAddress((void**)&peh1, g_eh1);
    cudaGetSymbolAddress((void**)&pez, g_ez);

    // CSR + batch ranges
    zero_prep<<<(Kk * Nn + 255) / 256, 256>>>();
    hist_deg<<<(Ee + 255) / 256, 256>>>(ei);
    scan_kernel<<<1, 1024>>>();
    csr_fill<<<(Ee + 255) / 256, 256>>>(ei);
    bstart_kernel<<<(Nn + 255) / 256, 256>>>(batch);

    // encoder GIN stack
    const float* hin = x;
    float* hbuf[2] = { ph0, ph1 };
    for (int l = 0; l < Ll; l++) {
        agg_enc<<<(Nn * 32 + 255) / 256, 256>>>(hin, enc_eps + l);
        mlp2_kernel<<<dim3(313, 1, 1), 256, 163840>>>(
            pz, hbuf[l & 1],
            enc_W1 + (size_t)l * 16384, enc_b1 + l * 128,
            enc_W2 + (size_t)l * 16384, enc_b2 + l * 128,
            Nn, 0, 0);
        hin = hbuf[l & 1];
    }
    // Z = g_h0 (l=2 -> buf 0)

    // mask MLP layer-1 precompute: P = Z @ [Wtop|Wbot] per expert (+b1 on top)
    gemm1_kernel<<<dim3(313, 8), 256, 98304>>>(ph0, mask_W1, mask_b1, Nn);

    // per-edge mask logits + gumbel + masks
    edge_mask_kernel<<<Ee / 8, 256>>>(ei, u, mask_W2, mask_b2, out);
    nodemask_kernel<<<(Nn + 255) / 256, 256>>>(out);
    maskedx_kernel<<<(Kk * Nn * 32) / 256, 256>>>(x);

    // expert GIN stacks (all K batched via blockIdx.z)
    const float* ehin = peh0;
    float* ebuf[2] = { peh1, peh0 };
    for (int l = 0; l < Ll; l++) {
        agg_exp<<<dim3((Nn * 32 + 255) / 256, 1, Kk), 256>>>(ehin, cls_eps + l);
        mlp2_kernel<<<dim3(313, 1, Kk), 256, 163840>>>(
            pez, ebuf[l & 1],
            cls_W1 + (size_t)l * 16384, cls_b1 + l * 128,
            cls_W2 + (size_t)l * 16384, cls_b2 + l * 128,
            Nn, Ll * 16384, Ll * 128);
        ehin = ebuf[l & 1];
    }
    // final expert h = g_eh1

    pool_kernel<<<dim3(Bb, Kk + 1), 512>>>(out);
    head_kernel<<<Kk, 128>>>(head_W1, head_b1, head_W2, head_b2, out);
}

// round 4
// speedup vs baseline: 1.0258x; 1.0258x over previous
#include <cuda_runtime.h>
#include <math.h>

#define Nn 20000
#define Ee 320000
#define Hh 128
#define Kk 4
#define Ll 3
#define Bb 64
#define Cc 2

#define NCH 160
#define CH  2000

// output layout (flattened tuple, row-major each)
#define OUT_LOGITS 0        // [B,K,C]   512
#define OUT_HSTAB  512      // [B,K,H]   32768
#define OUT_HORIG  33280    // [B,H]     8192
#define OUT_NM     41472    // [N,K,1]   80000
#define OUT_EM     121472   // [E,K,1]   1280000

// ---------------- scratch (static device arrays; no runtime alloc) ----------------
__device__ float g_h0[Nn * Hh];
__device__ float g_h1[Nn * Hh];
__device__ float g_z [Nn * Hh];
__device__ float g_P [(size_t)Nn * Kk * 2 * Hh];     // [N][8][128]
__device__ float g_eh0[(size_t)Kk * Nn * Hh];
__device__ float g_eh1[(size_t)Kk * Nn * Hh];
__device__ float g_ez [(size_t)Kk * Nn * Hh];
__device__ float g_emT[(size_t)Kk * Ee];             // transposed edge masks for agg
__device__ int   g_hist[(size_t)NCH * Nn];           // per-chunk dst histograms / prefix bases
__device__ int   g_deg[Nn];
__device__ int   g_off[Nn + 1];
__device__ int   g_csr_src[Ee];
__device__ int   g_csr_eid[Ee];
__device__ int   g_nwflag[Kk * Nn];
__device__ int   g_bstart[Bb + 1];

// ---------------- deterministic CSR build ----------------
__global__ void zero_prep2() {
    size_t i = (size_t)blockIdx.x * blockDim.x + threadIdx.x;
    if (i < (size_t)NCH * Nn) g_hist[i] = 0;
    if (i < (size_t)Kk * Nn) g_nwflag[i] = 0;
}

__global__ void hist_chunk(const int* __restrict__ ei) {
    int e = blockIdx.x * blockDim.x + threadIdx.x;
    if (e < Ee) atomicAdd(&g_hist[(size_t)(e / CH) * Nn + ei[Ee + e]], 1);
}

// per-node exclusive prefix over chunks -> g_hist becomes chunk base; g_deg = total
__global__ void chunk_scan() {
    int n = blockIdx.x * blockDim.x + threadIdx.x;
    if (n >= Nn) return;
    int run = 0;
#pragma unroll 4
    for (int c = 0; c < NCH; c++) {
        int t = g_hist[(size_t)c * Nn + n];
        g_hist[(size_t)c * Nn + n] = run;
        run += t;
    }
    g_deg[n] = run;
}

__global__ void scan_kernel() {
    __shared__ int sh[1024];
    __shared__ int carry;
    int tid = threadIdx.x;
    if (tid == 0) carry = 0;
    __syncthreads();
    for (int base = 0; base < Nn; base += 1024) {
        int i = base + tid;
        int v = (i < Nn) ? g_deg[i] : 0;
        sh[tid] = v;
        __syncthreads();
        for (int ofs = 1; ofs < 1024; ofs <<= 1) {
            int t = (tid >= ofs) ? sh[tid - ofs] : 0;
            __syncthreads();
            sh[tid] += t;
            __syncthreads();
        }
        int incl = sh[tid];
        int excl = incl - v;
        int c = carry;
        if (i < Nn) g_off[i] = c + excl;
        __syncthreads();
        if (tid == 1023) carry = c + incl;
        __syncthreads();
    }
    if (tid == 0) g_off[Nn] = carry;
}

// block per chunk: stable within-chunk rank via smem broadcast loop (deterministic)
__global__ void __launch_bounds__(1024, 1) fill_det(const int* __restrict__ ei) {
    __shared__ int sdst[CH];
    int c = blockIdx.x;
    int base = c * CH;
    int tid = threadIdx.x;
    for (int i = tid; i < CH; i += 1024) sdst[i] = ei[Ee + base + i];
    __syncthreads();
    for (int i = tid; i < CH; i += 1024) {
        int my = sdst[i];
        int rank = 0;
        for (int j = 0; j < i; j++) rank += (sdst[j] == my) ? 1 : 0;
        int pos = g_off[my] + g_hist[(size_t)c * Nn + my] + rank;
        g_csr_src[pos] = ei[base + i];
        g_csr_eid[pos] = base + i;
    }
}

__global__ void bstart_kernel(const int* __restrict__ batch) {
    int n = blockIdx.x * blockDim.x + threadIdx.x;
    if (n >= Nn) return;
    int bn = batch[n];
    if (n == 0) { for (int b = 0; b <= bn; b++) g_bstart[b] = 0; }
    else {
        int bp = batch[n - 1];
        for (int b = bp + 1; b <= bn; b++) g_bstart[b] = n;
    }
    if (n == Nn - 1) { for (int b = bn + 1; b <= Bb; b++) g_bstart[b] = Nn; }
}

// ---------------- aggregation (warp per node, CSR by dst) ----------------
__global__ void agg_enc(const float* __restrict__ hin, const float* __restrict__ epsp) {
    int w = (blockIdx.x * blockDim.x + threadIdx.x) >> 5;
    if (w >= Nn) return;
    int lane = threadIdx.x & 31;
    int col = lane * 4;
    int s = g_off[w], e = g_off[w + 1];
    float4 acc = make_float4(0.f, 0.f, 0.f, 0.f);
    for (int j = s; j < e; j++) {
        int sn = __ldg(&g_csr_src[j]);
        float4 v = *(const float4*)&hin[(size_t)sn * Hh + col];
        acc.x += v.x; acc.y += v.y; acc.z += v.z; acc.w += v.w;
    }
    float ep = 1.0f + __ldg(epsp);
    float4 hv = *(const float4*)&hin[(size_t)w * Hh + col];
    float4 z;
    z.x = fmaf(ep, hv.x, acc.x); z.y = fmaf(ep, hv.y, acc.y);
    z.z = fmaf(ep, hv.z, acc.z); z.w = fmaf(ep, hv.w, acc.w);
    *(float4*)&g_z[(size_t)w * Hh + col] = z;
}

__global__ void agg_exp(const float* __restrict__ hin, const float* __restrict__ epsp) {
    int k = blockIdx.z;
    int w = (blockIdx.x * blockDim.x + threadIdx.x) >> 5;
    if (w >= Nn) return;
    int lane = threadIdx.x & 31;
    int col = lane * 4;
    int s = g_off[w], e = g_off[w + 1];
    const float* hk = hin + (size_t)k * Nn * Hh;
    const float* emk = g_emT + (size_t)k * Ee;
    float4 acc = make_float4(0.f, 0.f, 0.f, 0.f);
    for (int j = s; j < e; j++) {
        int sn = __ldg(&g_csr_src[j]);
        int eid = __ldg(&g_csr_eid[j]);
        float wt = __ldg(&emk[eid]);
        if (wt != 0.0f) {
            float4 v = *(const float4*)&hk[(size_t)sn * Hh + col];
            acc.x = fmaf(wt, v.x, acc.x); acc.y = fmaf(wt, v.y, acc.y);
            acc.z = fmaf(wt, v.z, acc.z); acc.w = fmaf(wt, v.w, acc.w);
        }
    }
    float ep = 1.0f + __ldg(&epsp[k * Ll]);
    float4 hv = *(const float4*)&hk[(size_t)w * Hh + col];
    float4 z;
    z.x = fmaf(ep, hv.x, acc.x); z.y = fmaf(ep, hv.y, acc.y);
    z.z = fmaf(ep, hv.z, acc.z); z.w = fmaf(ep, hv.w, acc.w);
    *(float4*)&g_ez[((size_t)k * Nn + w) * Hh + col] = z;
}

// ---------------- fused 2-layer MLP (scalar fp32, exact): encoder path ----------------
__global__ void __launch_bounds__(256, 1)
mlp2_kernel(const float* __restrict__ zin, float* __restrict__ hout,
            const float* __restrict__ W1, const float* __restrict__ b1,
            const float* __restrict__ W2, const float* __restrict__ b2,
            int M) {
    extern __shared__ float sm[];
    float* w1s = sm;          // 16384
    float* w2s = sm + 16384;  // 16384
    float* ts  = sm + 32768;  // 64*128 = 8192
    int tid = threadIdx.x;

    for (int i = tid * 4; i < 16384; i += 1024) {
        *(float4*)&w1s[i] = *(const float4*)&W1[i];
        *(float4*)&w2s[i] = *(const float4*)&W2[i];
    }
    int row0 = blockIdx.x * 64;
    for (int i = tid * 4; i < 8192; i += 1024) {
        int r = i >> 7, c = i & 127;
        int gr = row0 + r;
        float4 v = make_float4(0.f, 0.f, 0.f, 0.f);
        if (gr < M) v = *(const float4*)&zin[(size_t)gr * Hh + c];
        *(float4*)&ts[i] = v;
    }
    __syncthreads();

    int wr = tid >> 5, lane = tid & 31;
    int r0 = wr * 8, c0 = lane * 4;
    float acc[8][4];
    float bx = b1[c0], by = b1[c0 + 1], bz = b1[c0 + 2], bw = b1[c0 + 3];
#pragma unroll
    for (int i = 0; i < 8; i++) { acc[i][0] = bx; acc[i][1] = by; acc[i][2] = bz; acc[i][3] = bw; }
    for (int kk = 0; kk < 128; kk++) {
        float4 w = *(float4*)&w1s[kk * 128 + c0];
#pragma unroll
        for (int i = 0; i < 8; i++) {
            float zv = ts[(r0 + i) * 128 + kk];
            acc[i][0] = fmaf(zv, w.x, acc[i][0]);
            acc[i][1] = fmaf(zv, w.y, acc[i][1]);
            acc[i][2] = fmaf(zv, w.z, acc[i][2]);
            acc[i][3] = fmaf(zv, w.w, acc[i][3]);
        }
    }
    __syncthreads();
#pragma unroll
    for (int i = 0; i < 8; i++) {
        float4 h;
        h.x = fmaxf(acc[i][0], 0.f); h.y = fmaxf(acc[i][1], 0.f);
        h.z = fmaxf(acc[i][2], 0.f); h.w = fmaxf(acc[i][3], 0.f);
        *(float4*)&ts[(r0 + i) * 128 + c0] = h;
    }
    __syncthreads();

    bx = b2[c0]; by = b2[c0 + 1]; bz = b2[c0 + 2]; bw = b2[c0 + 3];
#pragma unroll
    for (int i = 0; i < 8; i++) { acc[i][0] = bx; acc[i][1] = by; acc[i][2] = bz; acc[i][3] = bw; }
    for (int kk = 0; kk < 128; kk++) {
        float4 w = *(float4*)&w2s[kk * 128 + c0];
#pragma unroll
        for (int i = 0; i < 8; i++) {
            float zv = ts[(r0 + i) * 128 + kk];
            acc[i][0] = fmaf(zv, w.x, acc[i][0]);
            acc[i][1] = fmaf(zv, w.y, acc[i][1]);
            acc[i][2] = fmaf(zv, w.z, acc[i][2]);
            acc[i][3] = fmaf(zv, w.w, acc[i][3]);
        }
    }
#pragma unroll
    for (int i = 0; i < 8; i++) {
        int gr = row0 + r0 + i;
        if (gr < M) {
            float4 h;
            h.x = fmaxf(acc[i][0], 0.f); h.y = fmaxf(acc[i][1], 0.f);
            h.z = fmaxf(acc[i][2], 0.f); h.w = fmaxf(acc[i][3], 0.f);
            *(float4*)&hout[(size_t)gr * Hh + c0] = h;
        }
    }
}

// ---------------- 3xTF32 tensor-core fused 2-layer MLP: expert path ----------------
#define WP 132
#define SMEM_TC3 ((128 * WP * 2 + 64 * WP * 2) * 4)

__device__ __forceinline__ unsigned cvt_tf32(float x) {
    unsigned r;
    asm("cvt.rna.tf32.f32 %0, %1;" : "=r"(r) : "f"(x));
    return r;
}

__device__ __forceinline__ void mma_tf32(float acc[4], unsigned a0, unsigned a1,
                                         unsigned a2, unsigned a3, unsigned b0, unsigned b1) {
    asm("mma.sync.aligned.m16n8k8.row.col.f32.tf32.tf32.f32 "
        "{%0,%1,%2,%3}, {%4,%5,%6,%7}, {%8,%9}, {%0,%1,%2,%3};"
        : "+f"(acc[0]), "+f"(acc[1]), "+f"(acc[2]), "+f"(acc[3])
        : "r"(a0), "r"(a1), "r"(a2), "r"(a3), "r"(b0), "r"(b1));
}

__device__ __forceinline__ void tc3_pass(const float* __restrict__ whi, const float* __restrict__ wlo,
                                         const float* __restrict__ ahi, const float* __restrict__ alo,
                                         const float* __restrict__ bias,
                                         int m0, int nb, int q, int r4, float acc[8][4]) {
#pragma unroll
    for (int j = 0; j < 8; j++) {
        float bx = bias[nb + j * 8 + r4 * 2];
        float by = bias[nb + j * 8 + r4 * 2 + 1];
        acc[j][0] = bx; acc[j][1] = by; acc[j][2] = bx; acc[j][3] = by;
    }
    int ar = m0 + q;
#pragma unroll 2
    for (int s = 0; s < 16; s++) {
        int k0 = s * 8;
        unsigned ah0 = __float_as_uint(ahi[ar * WP + k0 + r4]);
        unsigned ah1 = __float_as_uint(ahi[(ar + 8) * WP + k0 + r4]);
        unsigned ah2 = __float_as_uint(ahi[ar * WP + k0 + r4 + 4]);
        unsigned ah3 = __float_as_uint(ahi[(ar + 8) * WP + k0 + r4 + 4]);
        unsigned al0 = __float_as_uint(alo[ar * WP + k0 + r4]);
        unsigned al1 = __float_as_uint(alo[(ar + 8) * WP + k0 + r4]);
        unsigned al2 = __float_as_uint(alo[ar * WP + k0 + r4 + 4]);
        unsigned al3 = __float_as_uint(alo[(ar + 8) * WP + k0 + r4 + 4]);
#pragma unroll
        for (int j = 0; j < 8; j++) {
            int wrow = (nb + j * 8 + q) * WP + k0 + r4;
            unsigned bh0 = __float_as_uint(whi[wrow]);
            unsigned bh1 = __float_as_uint(whi[wrow + 4]);
            unsigned bl0 = __float_as_uint(wlo[wrow]);
            unsigned bl1 = __float_as_uint(wlo[wrow + 4]);
            mma_tf32(acc[j], al0, al1, al2, al3, bh0, bh1);
            mma_tf32(acc[j], ah0, ah1, ah2, ah3, bl0, bl1);
            mma_tf32(acc[j], ah0, ah1, ah2, ah3, bh0, bh1);
        }
    }
}

__global__ void __launch_bounds__(256, 1)
mlp2_tc3(const float* __restrict__ zin, float* __restrict__ hout,
         const float* __restrict__ W1, const float* __restrict__ b1,
         const float* __restrict__ W2, const float* __restrict__ b2,
         int M, int wstride, int bstride) {
    extern __shared__ float sm[];
    float* whi = sm;                       // 128*132
    float* wlo = sm + 128 * WP;            // 128*132
    float* ahi = sm + 256 * WP;            // 64*132
    float* alo = sm + 256 * WP + 64 * WP;  // 64*132
    int k = blockIdx.z;
    const float* W1k = W1 + (size_t)k * wstride;
    const float* W2k = W2 + (size_t)k * wstride;
    const float* b1k = b1 + (size_t)k * bstride;
    const float* b2k = b2 + (size_t)k * bstride;
    const float* zk  = zin  + (size_t)k * M * Hh;
    float*       hk  = hout + (size_t)k * M * Hh;
    int tid = threadIdx.x;

    // W1: transpose to [n][k] + hi/lo split
    for (int i = tid; i < 16384; i += 256) {
        int kk = i >> 7, n = i & 127;
        float w = __ldg(&W1k[i]);
        unsigned h = cvt_tf32(w);
        float lo = w - __uint_as_float(h);
        whi[n * WP + kk] = __uint_as_float(h);
        wlo[n * WP + kk] = __uint_as_float(cvt_tf32(lo));
    }
    int row0 = blockIdx.x * 64;
    for (int i = tid * 4; i < 8192; i += 1024) {
        int r = i >> 7, c = i & 127;
        int gr = row0 + r;
        float4 v = make_float4(0.f, 0.f, 0.f, 0.f);
        if (gr < M) v = *(const float4*)&zk[(size_t)gr * Hh + c];
        uint4 hi4, lo4;
        hi4.x = cvt_tf32(v.x); lo4.x = cvt_tf32(v.x - __uint_as_float(hi4.x));
        hi4.y = cvt_tf32(v.y); lo4.y = cvt_tf32(v.y - __uint_as_float(hi4.y));
        hi4.z = cvt_tf32(v.z); lo4.z = cvt_tf32(v.z - __uint_as_float(hi4.z));
        hi4.w = cvt_tf32(v.w); lo4.w = cvt_tf32(v.w - __uint_as_float(hi4.w));
        *(uint4*)&ahi[r * WP + c] = hi4;
        *(uint4*)&alo[r * WP + c] = lo4;
    }
    __syncthreads();

    int wid = tid >> 5, lane = tid & 31;
    int wm = wid & 3, wn = wid >> 2;
    int m0 = wm * 16, nb = wn * 64;
    int q = lane >> 2, r4 = lane & 3;
    float acc[8][4];

    tc3_pass(whi, wlo, ahi, alo, b1k, m0, nb, q, r4, acc);
    __syncthreads();

    // overwrite weights with W2; store relu(hidden) back as hi/lo
    for (int i = tid; i < 16384; i += 256) {
        int kk = i >> 7, n = i & 127;
        float w = __ldg(&W2k[i]);
        unsigned h = cvt_tf32(w);
        float lo = w - __uint_as_float(h);
        whi[n * WP + kk] = __uint_as_float(h);
        wlo[n * WP + kk] = __uint_as_float(cvt_tf32(lo));
    }
    int hr = m0 + q;
#pragma unroll
    for (int j = 0; j < 8; j++) {
        int col = nb + j * 8 + r4 * 2;
        float h00 = fmaxf(acc[j][0], 0.f), h01 = fmaxf(acc[j][1], 0.f);
        float h10 = fmaxf(acc[j][2], 0.f), h11 = fmaxf(acc[j][3], 0.f);
        uint2 hi, lo;
        hi.x = cvt_tf32(h00); lo.x = cvt_tf32(h00 - __uint_as_float(hi.x));
        hi.y = cvt_tf32(h01); lo.y = cvt_tf32(h01 - __uint_as_float(hi.y));
        *(uint2*)&ahi[hr * WP + col] = hi;
        *(uint2*)&alo[hr * WP + col] = lo;
        hi.x = cvt_tf32(h10); lo.x = cvt_tf32(h10 - __uint_as_float(hi.x));
        hi.y = cvt_tf32(h11); lo.y = cvt_tf32(h11 - __uint_as_float(hi.y));
        *(uint2*)&ahi[(hr + 8) * WP + col] = hi;
        *(uint2*)&alo[(hr + 8) * WP + col] = lo;
    }
    __syncthreads();

    tc3_pass(whi, wlo, ahi, alo, b2k, m0, nb, q, r4, acc);

#pragma unroll
    for (int j = 0; j < 8; j++) {
        int col = nb + j * 8 + r4 * 2;
        int gr0 = row0 + m0 + q;
        if (gr0 < M) {
            float2 v = make_float2(fmaxf(acc[j][0], 0.f), fmaxf(acc[j][1], 0.f));
            *(float2*)&hk[(size_t)gr0 * Hh + col] = v;
        }
        int gr1 = gr0 + 8;
        if (gr1 < M) {
            float2 v = make_float2(fmaxf(acc[j][2], 0.f), fmaxf(acc[j][3], 0.f));
            *(float2*)&hk[(size_t)gr1 * Hh + col] = v;
        }
    }
}

// ---------------- single-layer GEMM (scalar fp32): P = Z @ [Wtop|Wbot] ----------------
__global__ void __launch_bounds__(256, 1)
gemm1_kernel(const float* __restrict__ zin, const float* __restrict__ mW1,
             const float* __restrict__ mb1, int M) {
    extern __shared__ float sm[];
    float* ws = sm;           // 16384
    float* ts = sm + 16384;   // 8192
    int ct = blockIdx.y;      // 0..7 : ct = 2*k + half
    int kq = ct >> 1, half = ct & 1;
    const float* Wt = mW1 + (size_t)ct * 16384;
    int tid = threadIdx.x;
    for (int i = tid * 4; i < 16384; i += 1024)
        *(float4*)&ws[i] = *(const float4*)&Wt[i];
    int row0 = blockIdx.x * 64;
    for (int i = tid * 4; i < 8192; i += 1024) {
        int r = i >> 7, c = i & 127;
        int gr = row0 + r;
        float4 v = make_float4(0.f, 0.f, 0.f, 0.f);
        if (gr < M) v = *(const float4*)&zin[(size_t)gr * Hh + c];
        *(float4*)&ts[i] = v;
    }
    __syncthreads();
    int wr = tid >> 5, lane = tid & 31;
    int r0 = wr * 8, c0 = lane * 4;
    float acc[8][4];
    float bx = 0.f, by = 0.f, bz = 0.f, bw = 0.f;
    if (half == 0) {
        bx = mb1[kq * 128 + c0];     by = mb1[kq * 128 + c0 + 1];
        bz = mb1[kq * 128 + c0 + 2]; bw = mb1[kq * 128 + c0 + 3];
    }
#pragma unroll
    for (int i = 0; i < 8; i++) { acc[i][0] = bx; acc[i][1] = by; acc[i][2] = bz; acc[i][3] = bw; }
    for (int kk = 0; kk < 128; kk++) {
        float4 w = *(float4*)&ws[kk * 128 + c0];
#pragma unroll
        for (int i = 0; i < 8; i++) {
            float zv = ts[(r0 + i) * 128 + kk];
            acc[i][0] = fmaf(zv, w.x, acc[i][0]);
            acc[i][1] = fmaf(zv, w.y, acc[i][1]);
            acc[i][2] = fmaf(zv, w.z, acc[i][2]);
            acc[i][3] = fmaf(zv, w.w, acc[i][3]);
        }
    }
#pragma unroll
    for (int i = 0; i < 8; i++) {
        int gr = row0 + r0 + i;
        if (gr < M) {
            float4 h; h.x = acc[i][0]; h.y = acc[i][1]; h.z = acc[i][2]; h.w = acc[i][3];
            *(float4*)&g_P[(size_t)gr * 1024 + ct * 128 + c0] = h;
        }
    }
}

// ---------------- edge masks (warp per edge, all K experts) ----------------
__global__ void edge_mask_kernel(const int* __restrict__ ei, const float* __restrict__ u,
                                 const float* __restrict__ mW2, const float* __restrict__ mb2,
                                 float* __restrict__ dout) {
    __shared__ float w2s[Kk * Hh];
    int tid = threadIdx.x;
    for (int i = tid; i < Kk * Hh; i += blockDim.x) w2s[i] = mW2[i];
    __syncthreads();
    int wid = tid >> 5, lane = tid & 31;
    int e = blockIdx.x * 8 + wid;
    if (e >= Ee) return;
    int src = ei[e], dst = ei[Ee + e];
    const float* Ps = g_P + (size_t)src * 1024;
    const float* Pd = g_P + (size_t)dst * 1024 + 128;
    float r[4];
#pragma unroll
    for (int k = 0; k < 4; k++) {
        float4 pt = *(const float4*)&Ps[k * 256 + lane * 4];
        float4 pb = *(const float4*)&Pd[k * 256 + lane * 4];
        float4 wv = *(const float4*)&w2s[k * 128 + lane * 4];
        float a = fmaxf(pt.x + pb.x, 0.f) * wv.x + fmaxf(pt.y + pb.y, 0.f) * wv.y
                + fmaxf(pt.z + pb.z, 0.f) * wv.z + fmaxf(pt.w + pb.w, 0.f) * wv.w;
#pragma unroll
        for (int o = 16; o > 0; o >>= 1) a += __shfl_xor_sync(0xffffffffu, a, o);
        r[k] = a;
    }
    if (lane < 4) {
        int k = lane;
        float em = r[k] + mb2[k];
        float uu = u[(size_t)e * Kk + k];
        float gmb = -logf(-logf(uu + 1e-20f) + 1e-20f);
        float t = (em + gmb) / 0.1f;
        float ys = 1.0f / (1.0f + expf(-t));
        float yh = (ys > 0.5f) ? 1.0f : 0.0f;
        float eo = (yh + ys) - ys;
        dout[OUT_EM + (size_t)e * Kk + k] = eo;
        g_emT[(size_t)k * Ee + e] = eo;
        if (eo > 0.0f) {
            g_nwflag[k * Nn + src] = 1;
            g_nwflag[k * Nn + dst] = 1;
        }
    }
}

__global__ void nodemask_kernel(float* __restrict__ dout) {
    int n = blockIdx.x * blockDim.x + threadIdx.x;
    if (n >= Nn) return;
    float4 v;
    v.x = g_nwflag[0 * Nn + n] ? 1.f : 0.f;
    v.y = g_nwflag[1 * Nn + n] ? 1.f : 0.f;
    v.z = g_nwflag[2 * Nn + n] ? 1.f : 0.f;
    v.w = g_nwflag[3 * Nn + n] ? 1.f : 0.f;
    *(float4*)&dout[OUT_NM + (size_t)n * 4] = v;
}

__global__ void maskedx_kernel(const float* __restrict__ x) {
    size_t i = (size_t)blockIdx.x * blockDim.x + threadIdx.x;
    if (i >= (size_t)Kk * Nn * 32) return;
    size_t kn = i >> 5;
    int col = (int)(i & 31) * 4;
    size_t n = kn % Nn;
    float4 xv = *(const float4*)&x[n * Hh + col];
    if (!g_nwflag[kn]) xv = make_float4(0.f, 0.f, 0.f, 0.f);
    *(float4*)&g_eh0[kn * Hh + col] = xv;
}

// ---------------- pooling + head ----------------
__global__ void pool_kernel(float* __restrict__ dout) {
    int b = blockIdx.x, which = blockIdx.y;
    int part = threadIdx.x >> 7;       // 0..3
    int f = threadIdx.x & 127;
    __shared__ float red[4][128];
    int s = g_bstart[b], e = g_bstart[b + 1];
    int cnt = e - s;
    const float* src;
    float* dp;
    if (which == Kk) { src = g_h0; dp = dout + OUT_HORIG + (size_t)b * Hh; }
    else {
        src = g_eh1 + (size_t)which * Nn * Hh;
        dp = dout + OUT_HSTAB + (size_t)b * (Kk * Hh) + which * Hh;
    }
    int chunk = (cnt + 3) >> 2;
    int ps = s + part * chunk;
    int pe = ps + chunk; if (pe > e) pe = e;
    float acc = 0.f;
    for (int n = ps; n < pe; n++) acc += src[(size_t)n * Hh + f];
    red[part][f] = acc;
    __syncthreads();
    if (part == 0) {
        float v = red[0][f] + red[1][f] + red[2][f] + red[3][f];
        dp[f] = v / fmaxf((float)cnt, 1.0f);
    }
}

__global__ void head_kernel(const float* __restrict__ hW1, const float* __restrict__ hb1,
                            const float* __restrict__ hW2, const float* __restrict__ hb2,
                            float* __restrict__ dout) {
    int k = blockIdx.x, f = threadIdx.x;
    __shared__ float hid[Bb][Hh];
    const float* hs = dout + OUT_HSTAB;
    const float* W1 = hW1 + (size_t)k * Hh * Hh;
    for (int b = 0; b < Bb; b++) {
        float acc = hb1[k * Hh + f];
        for (int i = 0; i < Hh; i++)
            acc = fmaf(hs[(size_t)b * (Kk * Hh) + k * Hh + i], W1[i * Hh + f], acc);
        hid[b][f] = fmaxf(acc, 0.f);
    }
    __syncthreads();
    int b = f >> 1, c = f & 1;
    const float* W2 = hW2 + (size_t)k * Hh * Cc;
    float acc = hb2[k * Cc + c];
    for (int i = 0; i < Hh; i++)
        acc = fmaf(hid[b][i], W2[i * Cc + c], acc);
    dout[OUT_LOGITS + (size_t)b * (Kk * Cc) + k * Cc + c] = acc;
}

// ---------------- launch ----------------
extern "C" void kernel_launch(void* const* d_in, const int* in_sizes, int n_in,
                              void* d_out, int out_size) {
    const float* x       = (const float*)d_in[0];
    const int*   ei      = (const int*)d_in[1];
    const int*   batch   = (const int*)d_in[2];
    const float* u       = (const float*)d_in[3];
    const float* enc_W1  = (const float*)d_in[4];
    const float* enc_b1  = (const float*)d_in[5];
    const float* enc_W2  = (const float*)d_in[6];
    const float* enc_b2  = (const float*)d_in[7];
    const float* enc_eps = (const float*)d_in[8];
    const float* cls_W1  = (const float*)d_in[9];
    const float* cls_b1  = (const float*)d_in[10];
    const float* cls_W2  = (const float*)d_in[11];
    const float* cls_b2  = (const float*)d_in[12];
    const float* cls_eps = (const float*)d_in[13];
    const float* mask_W1 = (const float*)d_in[14];
    const float* mask_b1 = (const float*)d_in[15];
    const float* mask_W2 = (const float*)d_in[16];
    const float* mask_b2 = (const float*)d_in[17];
    const float* head_W1 = (const float*)d_in[18];
    const float* head_b1 = (const float*)d_in[19];
    const float* head_W2 = (const float*)d_in[20];
    const float* head_b2 = (const float*)d_in[21];
    float* out = (float*)d_out;

    cudaFuncSetAttribute(mlp2_kernel, cudaFuncAttributeMaxDynamicSharedMemorySize, 163840);
    cudaFuncSetAttribute(gemm1_kernel, cudaFuncAttributeMaxDynamicSharedMemorySize, 98304);
    cudaFuncSetAttribute(mlp2_tc3, cudaFuncAttributeMaxDynamicSharedMemorySize, SMEM_TC3);

    float *ph0, *ph1, *pz, *peh0, *peh1, *pez;
    cudaGetSymbolAddress((void**)&ph0, g_h0);
    cudaGetSymbolAddress((void**)&ph1, g_h1);
    cudaGetSymbolAddress((void**)&pz, g_z);
    cudaGetSymbolAddress((void**)&peh0, g_eh0);
    cudaGetSymbolAddress((void**)&peh1, g_eh1);
    cudaGetSymbolAddress((void**)&pez, g_ez);

    // deterministic CSR + batch ranges
    zero_prep2<<<((size_t)NCH * Nn + 255) / 256, 256>>>();
    hist_chunk<<<(Ee + 255) / 256, 256>>>(ei);
    chunk_scan<<<(Nn + 255) / 256, 256>>>();
    scan_kernel<<<1, 1024>>>();
    fill_det<<<NCH, 1024>>>(ei);
    bstart_kernel<<<(Nn + 255) / 256, 256>>>(batch);

    // encoder GIN stack (exact fp32 — feeds the mask threshold path)
    const float* hin = x;
    float* hbuf[2] = { ph0, ph1 };
    for (int l = 0; l < Ll; l++) {
        agg_enc<<<(Nn * 32 + 255) / 256, 256>>>(hin, enc_eps + l);
        mlp2_kernel<<<dim3(313, 1, 1), 256, 163840>>>(
            pz, hbuf[l & 1],
            enc_W1 + (size_t)l * 16384, enc_b1 + l * 128,
            enc_W2 + (size_t)l * 16384, enc_b2 + l * 128,
            Nn);
        hin = hbuf[l & 1];
    }
    // Z = g_h0 (l=2 -> buf 0)

    // mask MLP layer-1 precompute: P = Z @ [Wtop|Wbot] per expert (+b1 on top)
    gemm1_kernel<<<dim3(313, 8), 256, 98304>>>(ph0, mask_W1, mask_b1, Nn);

    // per-edge mask logits + gumbel + masks
    edge_mask_kernel<<<Ee / 8, 256>>>(ei, u, mask_W2, mask_b2, out);
    nodemask_kernel<<<(Nn + 255) / 256, 256>>>(out);
    maskedx_kernel<<<(Kk * Nn * 32) / 256, 256>>>(x);

    // expert GIN stacks (3xTF32 tensor cores; ~fp32 accuracy)
    const float* ehin = peh0;
    float* ebuf[2] = { peh1, peh0 };
    for (int l = 0; l < Ll; l++) {
        agg_exp<<<dim3((Nn * 32 + 255) / 256, 1, Kk), 256>>>(ehin, cls_eps + l);
        mlp2_tc3<<<dim3(313, 1, Kk), 256, SMEM_TC3>>>(
            pez, ebuf[l & 1],
            cls_W1 + (size_t)l * 16384, cls_b1 + l * 128,
            cls_W2 + (size_t)l * 16384, cls_b2 + l * 128,
            Nn, Ll * 16384, Ll * 128);
        ehin = ebuf[l & 1];
    }
    // final expert h = g_eh1

    pool_kernel<<<dim3(Bb, Kk + 1), 512>>>(out);
    head_kernel<<<Kk, 128>>>(head_W1, head_b1, head_W2, head_b2, out);
}

// round 5
// speedup vs baseline: 1.0567x; 1.0301x over previous
#include <cuda_runtime.h>
#include <math.h>

#define Nn 20000
#define Ee 320000
#define Hh 128
#define Kk 4
#define Ll 3
#define Bb 64
#define Cc 2

#define NCH 160
#define CH  2000
#define WP  132

// output layout (flattened tuple, row-major each)
#define OUT_LOGITS 0        // [B,K,C]   512
#define OUT_HSTAB  512      // [B,K,H]   32768
#define OUT_HORIG  33280    // [B,H]     8192
#define OUT_NM     41472    // [N,K,1]   80000
#define OUT_EM     121472   // [E,K,1]   1280000

// ---------------- scratch (static device arrays; no runtime alloc) ----------------
__device__ float g_h0[Nn * Hh];
__device__ float g_h1[Nn * Hh];
__device__ float g_z [Nn * Hh];
__device__ float g_P [(size_t)Nn * Kk * 2 * Hh];     // [N][8][128]
__device__ float g_eh0[(size_t)Kk * Nn * Hh];
__device__ float g_eh1[(size_t)Kk * Nn * Hh];
__device__ float g_ez [(size_t)Kk * Nn * Hh];
__device__ float g_emT[(size_t)Kk * Ee];             // transposed edge masks for agg
__device__ float g_wt [(size_t)Kk * Ll * 2 * 2 * 128 * WP];  // pre-transposed hi/lo expert weights
__device__ int   g_hist[(size_t)NCH * Nn];           // per-chunk dst histograms / prefix bases
__device__ int   g_deg[Nn];
__device__ int   g_off[Nn + 1];
__device__ int   g_bsum[32];
__device__ int   g_bbase[32];
__device__ int   g_csr_src[Ee];
__device__ int   g_csr_eid[Ee];
__device__ int   g_nwflag[Kk * Nn];
__device__ int   g_bstart[Bb + 1];

// ---------------- deterministic CSR build ----------------
__global__ void zero_prep2() {
    size_t i = (size_t)blockIdx.x * blockDim.x + threadIdx.x;
    if (i < (size_t)NCH * Nn) g_hist[i] = 0;
    if (i < (size_t)Kk * Nn) g_nwflag[i] = 0;
}

__global__ void hist_chunk(const int* __restrict__ ei) {
    int e = blockIdx.x * blockDim.x + threadIdx.x;
    if (e < Ee) atomicAdd(&g_hist[(size_t)(e / CH) * Nn + ei[Ee + e]], 1);
}

// per-node exclusive prefix over chunks -> g_hist becomes chunk base; g_deg = total
__global__ void chunk_scan() {
    int n = blockIdx.x * blockDim.x + threadIdx.x;
    if (n >= Nn) return;
    int run = 0;
#pragma unroll 4
    for (int c = 0; c < NCH; c++) {
        int t = g_hist[(size_t)c * Nn + n];
        g_hist[(size_t)c * Nn + n] = run;
        run += t;
    }
    g_deg[n] = run;
}

// two-level scan over g_deg -> g_off (exclusive)
__global__ void scan_a() {
    __shared__ int sh[1024];
    int b = blockIdx.x, tid = threadIdx.x;
    int i = b * 1024 + tid;
    int v = (i < Nn) ? g_deg[i] : 0;
    sh[tid] = v;
    __syncthreads();
    for (int ofs = 1; ofs < 1024; ofs <<= 1) {
        int t = (tid >= ofs) ? sh[tid - ofs] : 0;
        __syncthreads();
        sh[tid] += t;
        __syncthreads();
    }
    if (i < Nn) g_off[i] = sh[tid] - v;      // block-local exclusive
    if (tid == 1023) g_bsum[b] = sh[1023];
}

__global__ void scan_b(int nblk) {
    int tid = threadIdx.x;
    int v = (tid < nblk) ? g_bsum[tid] : 0;
    int run = 0;
    for (int j = 0; j < 32; j++) {
        int t = __shfl_sync(0xffffffffu, v, j);
        if (tid == j) { g_bbase[j] = run; }
        run += t;
    }
    if (tid == 0) g_off[Nn] = run;
}

__global__ void scan_c() {
    int i = blockIdx.x * blockDim.x + threadIdx.x;
    if (i < Nn) g_off[i] += g_bbase[i >> 10];
}

// block per chunk: stable within-chunk rank via smem broadcast loop (deterministic)
__global__ void __launch_bounds__(1024, 1) fill_det(const int* __restrict__ ei) {
    __shared__ int sdst[CH];
    int c = blockIdx.x;
    int base = c * CH;
    int tid = threadIdx.x;
    for (int i = tid; i < CH; i += 1024) sdst[i] = ei[Ee + base + i];
    __syncthreads();
    for (int i = tid; i < CH; i += 1024) {
        int my = sdst[i];
        int rank = 0;
        for (int j = 0; j < i; j++) rank += (sdst[j] == my) ? 1 : 0;
        int pos = g_off[my] + g_hist[(size_t)c * Nn + my] + rank;
        g_csr_src[pos] = ei[base + i];
        g_csr_eid[pos] = base + i;
    }
}

__global__ void bstart_kernel(const int* __restrict__ batch) {
    int n = blockIdx.x * blockDim.x + threadIdx.x;
    if (n >= Nn) return;
    int bn = batch[n];
    if (n == 0) { for (int b = 0; b <= bn; b++) g_bstart[b] = 0; }
    else {
        int bp = batch[n - 1];
        for (int b = bp + 1; b <= bn; b++) g_bstart[b] = n;
    }
    if (n == Nn - 1) { for (int b = bn + 1; b <= Bb; b++) g_bstart[b] = Nn; }
}

// ---------------- tf32 helpers + expert weight pre-transpose ----------------
__device__ __forceinline__ unsigned cvt_tf32(float x) {
    unsigned r;
    asm("cvt.rna.tf32.f32 %0, %1;" : "=r"(r) : "f"(x));
    return r;
}

// g_wt layout: [(k*Ll+l)*2+ly][hilo][n*WP+kk], each array 128*WP floats
__global__ void prep_wt(const float* __restrict__ cW1, const float* __restrict__ cW2) {
    int idx = blockIdx.x * blockDim.x + threadIdx.x;
    if (idx >= Kk * Ll * 2 * 16384) return;
    int widx = idx >> 14;         // (k*Ll+l)*2+ly
    int r = idx & 16383;
    int n = r >> 7, kk = r & 127;
    int ly = widx & 1, kl = widx >> 1;
    const float* W = (ly == 0 ? cW1 : cW2) + (size_t)kl * 16384;
    float w = __ldg(&W[kk * 128 + n]);
    unsigned h = cvt_tf32(w);
    float lo = w - __uint_as_float(h);
    size_t base = (size_t)widx * 2 * 128 * WP;
    g_wt[base + (size_t)n * WP + kk] = __uint_as_float(h);
    g_wt[base + 128 * WP + (size_t)n * WP + kk] = __uint_as_float(cvt_tf32(lo));
}

// ---------------- aggregation (warp per node, CSR by dst) ----------------
__global__ void agg_enc(const float* __restrict__ hin, const float* __restrict__ epsp) {
    int w = (blockIdx.x * blockDim.x + threadIdx.x) >> 5;
    if (w >= Nn) return;
    int lane = threadIdx.x & 31;
    int col = lane * 4;
    int s = g_off[w], e = g_off[w + 1];
    float4 acc = make_float4(0.f, 0.f, 0.f, 0.f);
    for (int j = s; j < e; j++) {
        int sn = __ldg(&g_csr_src[j]);
        float4 v = *(const float4*)&hin[(size_t)sn * Hh + col];
        acc.x += v.x; acc.y += v.y; acc.z += v.z; acc.w += v.w;
    }
    float ep = 1.0f + __ldg(epsp);
    float4 hv = *(const float4*)&hin[(size_t)w * Hh + col];
    float4 z;
    z.x = fmaf(ep, hv.x, acc.x); z.y = fmaf(ep, hv.y, acc.y);
    z.z = fmaf(ep, hv.z, acc.z); z.w = fmaf(ep, hv.w, acc.w);
    *(float4*)&g_z[(size_t)w * Hh + col] = z;
}

__global__ void agg_exp(const float* __restrict__ hin, const float* __restrict__ epsp) {
    int k = blockIdx.z;
    int w = (blockIdx.x * blockDim.x + threadIdx.x) >> 5;
    if (w >= Nn) return;
    int lane = threadIdx.x & 31;
    int col = lane * 4;
    int s = g_off[w], e = g_off[w + 1];
    const float* hk = hin + (size_t)k * Nn * Hh;
    const float* emk = g_emT + (size_t)k * Ee;
    float4 acc = make_float4(0.f, 0.f, 0.f, 0.f);
    for (int j = s; j < e; j++) {
        int sn = __ldg(&g_csr_src[j]);
        int eid = __ldg(&g_csr_eid[j]);
        float wt = __ldg(&emk[eid]);
        if (wt != 0.0f) {
            float4 v = *(const float4*)&hk[(size_t)sn * Hh + col];
            acc.x = fmaf(wt, v.x, acc.x); acc.y = fmaf(wt, v.y, acc.y);
            acc.z = fmaf(wt, v.z, acc.z); acc.w = fmaf(wt, v.w, acc.w);
        }
    }
    float ep = 1.0f + __ldg(&epsp[k * Ll]);
    float4 hv = *(const float4*)&hk[(size_t)w * Hh + col];
    float4 z;
    z.x = fmaf(ep, hv.x, acc.x); z.y = fmaf(ep, hv.y, acc.y);
    z.z = fmaf(ep, hv.z, acc.z); z.w = fmaf(ep, hv.w, acc.w);
    *(float4*)&g_ez[((size_t)k * Nn + w) * Hh + col] = z;
}

// ---------------- fused 2-layer MLP (scalar fp32, exact): encoder path ----------------
__global__ void __launch_bounds__(256, 1)
mlp2_kernel(const float* __restrict__ zin, float* __restrict__ hout,
            const float* __restrict__ W1, const float* __restrict__ b1,
            const float* __restrict__ W2, const float* __restrict__ b2,
            int M) {
    extern __shared__ float sm[];
    float* w1s = sm;          // 16384
    float* w2s = sm + 16384;  // 16384
    float* ts  = sm + 32768;  // 64*128 = 8192
    int tid = threadIdx.x;

    for (int i = tid * 4; i < 16384; i += 1024) {
        *(float4*)&w1s[i] = *(const float4*)&W1[i];
        *(float4*)&w2s[i] = *(const float4*)&W2[i];
    }
    int row0 = blockIdx.x * 64;
    for (int i = tid * 4; i < 8192; i += 1024) {
        int r = i >> 7, c = i & 127;
        int gr = row0 + r;
        float4 v = make_float4(0.f, 0.f, 0.f, 0.f);
        if (gr < M) v = *(const float4*)&zin[(size_t)gr * Hh + c];
        *(float4*)&ts[i] = v;
    }
    __syncthreads();

    int wr = tid >> 5, lane = tid & 31;
    int r0 = wr * 8, c0 = lane * 4;
    float acc[8][4];
    float bx = b1[c0], by = b1[c0 + 1], bz = b1[c0 + 2], bw = b1[c0 + 3];
#pragma unroll
    for (int i = 0; i < 8; i++) { acc[i][0] = bx; acc[i][1] = by; acc[i][2] = bz; acc[i][3] = bw; }
    for (int kk = 0; kk < 128; kk++) {
        float4 w = *(float4*)&w1s[kk * 128 + c0];
#pragma unroll
        for (int i = 0; i < 8; i++) {
            float zv = ts[(r0 + i) * 128 + kk];
            acc[i][0] = fmaf(zv, w.x, acc[i][0]);
            acc[i][1] = fmaf(zv, w.y, acc[i][1]);
            acc[i][2] = fmaf(zv, w.z, acc[i][2]);
            acc[i][3] = fmaf(zv, w.w, acc[i][3]);
        }
    }
    __syncthreads();
#pragma unroll
    for (int i = 0; i < 8; i++) {
        float4 h;
        h.x = fmaxf(acc[i][0], 0.f); h.y = fmaxf(acc[i][1], 0.f);
        h.z = fmaxf(acc[i][2], 0.f); h.w = fmaxf(acc[i][3], 0.f);
        *(float4*)&ts[(r0 + i) * 128 + c0] = h;
    }
    __syncthreads();

    bx = b2[c0]; by = b2[c0 + 1]; bz = b2[c0 + 2]; bw = b2[c0 + 3];
#pragma unroll
    for (int i = 0; i < 8; i++) { acc[i][0] = bx; acc[i][1] = by; acc[i][2] = bz; acc[i][3] = bw; }
    for (int kk = 0; kk < 128; kk++) {
        float4 w = *(float4*)&w2s[kk * 128 + c0];
#pragma unroll
        for (int i = 0; i < 8; i++) {
            float zv = ts[(r0 + i) * 128 + kk];
            acc[i][0] = fmaf(zv, w.x, acc[i][0]);
            acc[i][1] = fmaf(zv, w.y, acc[i][1]);
            acc[i][2] = fmaf(zv, w.z, acc[i][2]);
            acc[i][3] = fmaf(zv, w.w, acc[i][3]);
        }
    }
#pragma unroll
    for (int i = 0; i < 8; i++) {
        int gr = row0 + r0 + i;
        if (gr < M) {
            float4 h;
            h.x = fmaxf(acc[i][0], 0.f); h.y = fmaxf(acc[i][1], 0.f);
            h.z = fmaxf(acc[i][2], 0.f); h.w = fmaxf(acc[i][3], 0.f);
            *(float4*)&hout[(size_t)gr * Hh + c0] = h;
        }
    }
}

// ---------------- 3xTF32 tensor-core fused 2-layer MLP: expert path ----------------
#define SMEM_TC3 ((128 * WP * 2 + 64 * WP * 2) * 4)

__device__ __forceinline__ void mma_tf32(float acc[4], unsigned a0, unsigned a1,
                                         unsigned a2, unsigned a3, unsigned b0, unsigned b1) {
    asm("mma.sync.aligned.m16n8k8.row.col.f32.tf32.tf32.f32 "
        "{%0,%1,%2,%3}, {%4,%5,%6,%7}, {%8,%9}, {%0,%1,%2,%3};"
        : "+f"(acc[0]), "+f"(acc[1]), "+f"(acc[2]), "+f"(acc[3])
        : "r"(a0), "r"(a1), "r"(a2), "r"(a3), "r"(b0), "r"(b1));
}

__device__ __forceinline__ void tc3_pass(const float* __restrict__ whi, const float* __restrict__ wlo,
                                         const float* __restrict__ ahi, const float* __restrict__ alo,
                                         const float* __restrict__ bias,
                                         int m0, int nb, int q, int r4, float acc[8][4]) {
#pragma unroll
    for (int j = 0; j < 8; j++) {
        float bx = bias[nb + j * 8 + r4 * 2];
        float by = bias[nb + j * 8 + r4 * 2 + 1];
        acc[j][0] = bx; acc[j][1] = by; acc[j][2] = bx; acc[j][3] = by;
    }
    int ar = m0 + q;
#pragma unroll 2
    for (int s = 0; s < 16; s++) {
        int k0 = s * 8;
        unsigned ah0 = __float_as_uint(ahi[ar * WP + k0 + r4]);
        unsigned ah1 = __float_as_uint(ahi[(ar + 8) * WP + k0 + r4]);
        unsigned ah2 = __float_as_uint(ahi[ar * WP + k0 + r4 + 4]);
        unsigned ah3 = __float_as_uint(ahi[(ar + 8) * WP + k0 + r4 + 4]);
        unsigned al0 = __float_as_uint(alo[ar * WP + k0 + r4]);
        unsigned al1 = __float_as_uint(alo[(ar + 8) * WP + k0 + r4]);
        unsigned al2 = __float_as_uint(alo[ar * WP + k0 + r4 + 4]);
        unsigned al3 = __float_as_uint(alo[(ar + 8) * WP + k0 + r4 + 4]);
#pragma unroll
        for (int j = 0; j < 8; j++) {
            int wrow = (nb + j * 8 + q) * WP + k0 + r4;
            unsigned bh0 = __float_as_uint(whi[wrow]);
            unsigned bh1 = __float_as_uint(whi[wrow + 4]);
            unsigned bl0 = __float_as_uint(wlo[wrow]);
            unsigned bl1 = __float_as_uint(wlo[wrow + 4]);
            mma_tf32(acc[j], al0, al1, al2, al3, bh0, bh1);
            mma_tf32(acc[j], ah0, ah1, ah2, ah3, bl0, bl1);
            mma_tf32(acc[j], ah0, ah1, ah2, ah3, bh0, bh1);
        }
    }
}

__global__ void __launch_bounds__(256, 1)
mlp2_tc3(const float* __restrict__ zin, float* __restrict__ hout,
         const float* __restrict__ b1, const float* __restrict__ b2,
         int lw, int M, int bstride) {
    extern __shared__ float sm[];
    float* whi = sm;                       // 128*WP
    float* wlo = sm + 128 * WP;            // 128*WP
    float* ahi = sm + 256 * WP;            // 64*WP
    float* alo = sm + 256 * WP + 64 * WP;  // 64*WP
    int k = blockIdx.z;
    const float* b1k = b1 + (size_t)k * bstride;
    const float* b2k = b2 + (size_t)k * bstride;
    const float* zk  = zin  + (size_t)k * M * Hh;
    float*       hk  = hout + (size_t)k * M * Hh;
    int tid = threadIdx.x;

    // W1: straight coalesced copy from pre-transposed global scratch
    const float* gw1 = g_wt + (size_t)((k * Ll + lw) * 2 + 0) * 2 * 128 * WP;
    for (int i = tid * 4; i < 128 * WP; i += 1024) {
        *(float4*)&whi[i] = *(const float4*)&gw1[i];
        *(float4*)&wlo[i] = *(const float4*)&gw1[128 * WP + i];
    }
    int row0 = blockIdx.x * 64;
    for (int i = tid * 4; i < 8192; i += 1024) {
        int r = i >> 7, c = i & 127;
        int gr = row0 + r;
        float4 v = make_float4(0.f, 0.f, 0.f, 0.f);
        if (gr < M) v = *(const float4*)&zk[(size_t)gr * Hh + c];
        uint4 hi4, lo4;
        hi4.x = cvt_tf32(v.x); lo4.x = cvt_tf32(v.x - __uint_as_float(hi4.x));
        hi4.y = cvt_tf32(v.y); lo4.y = cvt_tf32(v.y - __uint_as_float(hi4.y));
        hi4.z = cvt_tf32(v.z); lo4.z = cvt_tf32(v.z - __uint_as_float(hi4.z));
        hi4.w = cvt_tf32(v.w); lo4.w = cvt_tf32(v.w - __uint_as_float(hi4.w));
        *(uint4*)&ahi[r * WP + c] = hi4;
        *(uint4*)&alo[r * WP + c] = lo4;
    }
    __syncthreads();

    int wid = tid >> 5, lane = tid & 31;
    int wm = wid & 3, wn = wid >> 2;
    int m0 = wm * 16, nb = wn * 64;
    int q = lane >> 2, r4 = lane & 3;
    float acc[8][4];

    tc3_pass(whi, wlo, ahi, alo, b1k, m0, nb, q, r4, acc);
    __syncthreads();

    // W2: overwrite weights (coalesced copy); store relu(hidden) back as hi/lo
    const float* gw2 = g_wt + (size_t)((k * Ll + lw) * 2 + 1) * 2 * 128 * WP;
    for (int i = tid * 4; i < 128 * WP; i += 1024) {
        *(float4*)&whi[i] = *(const float4*)&gw2[i];
        *(float4*)&wlo[i] = *(const float4*)&gw2[128 * WP + i];
    }
    int hr = m0 + q;
#pragma unroll
    for (int j = 0; j < 8; j++) {
        int col = nb + j * 8 + r4 * 2;
        float h00 = fmaxf(acc[j][0], 0.f), h01 = fmaxf(acc[j][1], 0.f);
        float h10 = fmaxf(acc[j][2], 0.f), h11 = fmaxf(acc[j][3], 0.f);
        uint2 hi, lo;
        hi.x = cvt_tf32(h00); lo.x = cvt_tf32(h00 - __uint_as_float(hi.x));
        hi.y = cvt_tf32(h01); lo.y = cvt_tf32(h01 - __uint_as_float(hi.y));
        *(uint2*)&ahi[hr * WP + col] = hi;
        *(uint2*)&alo[hr * WP + col] = lo;
        hi.x = cvt_tf32(h10); lo.x = cvt_tf32(h10 - __uint_as_float(hi.x));
        hi.y = cvt_tf32(h11); lo.y = cvt_tf32(h11 - __uint_as_float(hi.y));
        *(uint2*)&ahi[(hr + 8) * WP + col] = hi;
        *(uint2*)&alo[(hr + 8) * WP + col] = lo;
    }
    __syncthreads();

    tc3_pass(whi, wlo, ahi, alo, b2k, m0, nb, q, r4, acc);

#pragma unroll
    for (int j = 0; j < 8; j++) {
        int col = nb + j * 8 + r4 * 2;
        int gr0 = row0 + m0 + q;
        if (gr0 < M) {
            float2 v = make_float2(fmaxf(acc[j][0], 0.f), fmaxf(acc[j][1], 0.f));
            *(float2*)&hk[(size_t)gr0 * Hh + col] = v;
        }
        int gr1 = gr0 + 8;
        if (gr1 < M) {
            float2 v = make_float2(fmaxf(acc[j][2], 0.f), fmaxf(acc[j][3], 0.f));
            *(float2*)&hk[(size_t)gr1 * Hh + col] = v;
        }
    }
}

// ---------------- single-layer GEMM (scalar fp32): P = Z @ [Wtop|Wbot] ----------------
__global__ void __launch_bounds__(256, 1)
gemm1_kernel(const float* __restrict__ zin, const float* __restrict__ mW1,
             const float* __restrict__ mb1, int M) {
    extern __shared__ float sm[];
    float* ws = sm;           // 16384
    float* ts = sm + 16384;   // 8192
    int ct = blockIdx.y;      // 0..7 : ct = 2*k + half
    int kq = ct >> 1, half = ct & 1;
    const float* Wt = mW1 + (size_t)ct * 16384;
    int tid = threadIdx.x;
    for (int i = tid * 4; i < 16384; i += 1024)
        *(float4*)&ws[i] = *(const float4*)&Wt[i];
    int row0 = blockIdx.x * 64;
    for (int i = tid * 4; i < 8192; i += 1024) {
        int r = i >> 7, c = i & 127;
        int gr = row0 + r;
        float4 v = make_float4(0.f, 0.f, 0.f, 0.f);
        if (gr < M) v = *(const float4*)&zin[(size_t)gr * Hh + c];
        *(float4*)&ts[i] = v;
    }
    __syncthreads();
    int wr = tid >> 5, lane = tid & 31;
    int r0 = wr * 8, c0 = lane * 4;
    float acc[8][4];
    float bx = 0.f, by = 0.f, bz = 0.f, bw = 0.f;
    if (half == 0) {
        bx = mb1[kq * 128 + c0];     by = mb1[kq * 128 + c0 + 1];
        bz = mb1[kq * 128 + c0 + 2]; bw = mb1[kq * 128 + c0 + 3];
    }
#pragma unroll
    for (int i = 0; i < 8; i++) { acc[i][0] = bx; acc[i][1] = by; acc[i][2] = bz; acc[i][3] = bw; }
    for (int kk = 0; kk < 128; kk++) {
        float4 w = *(float4*)&ws[kk * 128 + c0];
#pragma unroll
        for (int i = 0; i < 8; i++) {
            float zv = ts[(r0 + i) * 128 + kk];
            acc[i][0] = fmaf(zv, w.x, acc[i][0]);
            acc[i][1] = fmaf(zv, w.y, acc[i][1]);
            acc[i][2] = fmaf(zv, w.z, acc[i][2]);
            acc[i][3] = fmaf(zv, w.w, acc[i][3]);
        }
    }
#pragma unroll
    for (int i = 0; i < 8; i++) {
        int gr = row0 + r0 + i;
        if (gr < M) {
            float4 h; h.x = acc[i][0]; h.y = acc[i][1]; h.z = acc[i][2]; h.w = acc[i][3];
            *(float4*)&g_P[(size_t)gr * 1024 + ct * 128 + c0] = h;
        }
    }
}

// ---------------- edge masks (warp per edge, all K experts) ----------------
__global__ void edge_mask_kernel(const int* __restrict__ ei, const float* __restrict__ u,
                                 const float* __restrict__ mW2, const float* __restrict__ mb2,
                                 float* __restrict__ dout) {
    __shared__ float w2s[Kk * Hh];
    int tid = threadIdx.x;
    for (int i = tid; i < Kk * Hh; i += blockDim.x) w2s[i] = mW2[i];
    __syncthreads();
    int wid = tid >> 5, lane = tid & 31;
    int e = blockIdx.x * 8 + wid;
    if (e >= Ee) return;
    int src = ei[e], dst = ei[Ee + e];
    const float* Ps = g_P + (size_t)src * 1024;
    const float* Pd = g_P + (size_t)dst * 1024 + 128;
    float r[4];
#pragma unroll
    for (int k = 0; k < 4; k++) {
        float4 pt = *(const float4*)&Ps[k * 256 + lane * 4];
        float4 pb = *(const float4*)&Pd[k * 256 + lane * 4];
        float4 wv = *(const float4*)&w2s[k * 128 + lane * 4];
        float a = fmaxf(pt.x + pb.x, 0.f) * wv.x + fmaxf(pt.y + pb.y, 0.f) * wv.y
                + fmaxf(pt.z + pb.z, 0.f) * wv.z + fmaxf(pt.w + pb.w, 0.f) * wv.w;
#pragma unroll
        for (int o = 16; o > 0; o >>= 1) a += __shfl_xor_sync(0xffffffffu, a, o);
        r[k] = a;
    }
    if (lane < 4) {
        int k = lane;
        float em = r[k] + mb2[k];
        float uu = u[(size_t)e * Kk + k];
        float gmb = -logf(-logf(uu + 1e-20f) + 1e-20f);
        float t = (em + gmb) / 0.1f;
        float ys = 1.0f / (1.0f + expf(-t));
        float yh = (ys > 0.5f) ? 1.0f : 0.0f;
        float eo = (yh + ys) - ys;
        dout[OUT_EM + (size_t)e * Kk + k] = eo;
        g_emT[(size_t)k * Ee + e] = eo;
        if (eo > 0.0f) {
            g_nwflag[k * Nn + src] = 1;
            g_nwflag[k * Nn + dst] = 1;
        }
    }
}

__global__ void nodemask_kernel(float* __restrict__ dout) {
    int n = blockIdx.x * blockDim.x + threadIdx.x;
    if (n >= Nn) return;
    float4 v;
    v.x = g_nwflag[0 * Nn + n] ? 1.f : 0.f;
    v.y = g_nwflag[1 * Nn + n] ? 1.f : 0.f;
    v.z = g_nwflag[2 * Nn + n] ? 1.f : 0.f;
    v.w = g_nwflag[3 * Nn + n] ? 1.f : 0.f;
    *(float4*)&dout[OUT_NM + (size_t)n * 4] = v;
}

__global__ void maskedx_kernel(const float* __restrict__ x) {
    size_t i = (size_t)blockIdx.x * blockDim.x + threadIdx.x;
    if (i >= (size_t)Kk * Nn * 32) return;
    size_t kn = i >> 5;
    int col = (int)(i & 31) * 4;
    size_t n = kn % Nn;
    float4 xv = *(const float4*)&x[n * Hh + col];
    if (!g_nwflag[kn]) xv = make_float4(0.f, 0.f, 0.f, 0.f);
    *(float4*)&g_eh0[kn * Hh + col] = xv;
}

// ---------------- pooling + head ----------------
__global__ void pool_kernel(float* __restrict__ dout) {
    int b = blockIdx.x, which = blockIdx.y;
    int part = threadIdx.x >> 7;       // 0..3
    int f = threadIdx.x & 127;
    __shared__ float red[4][128];
    int s = g_bstart[b], e = g_bstart[b + 1];
    int cnt = e - s;
    const float* src;
    float* dp;
    if (which == Kk) { src = g_h0; dp = dout + OUT_HORIG + (size_t)b * Hh; }
    else {
        src = g_eh1 + (size_t)which * Nn * Hh;
        dp = dout + OUT_HSTAB + (size_t)b * (Kk * Hh) + which * Hh;
    }
    int chunk = (cnt + 3) >> 2;
    int ps = s + part * chunk;
    int pe = ps + chunk; if (pe > e) pe = e;
    float acc = 0.f;
    for (int n = ps; n < pe; n++) acc += src[(size_t)n * Hh + f];
    red[part][f] = acc;
    __syncthreads();
    if (part == 0) {
        float v = red[0][f] + red[1][f] + red[2][f] + red[3][f];
        dp[f] = v / fmaxf((float)cnt, 1.0f);
    }
}

__global__ void head_kernel(const float* __restrict__ hW1, const float* __restrict__ hb1,
                            const float* __restrict__ hW2, const float* __restrict__ hb2,
                            float* __restrict__ dout) {
    int k = blockIdx.x, f = threadIdx.x;
    __shared__ float hid[Bb][Hh];
    const float* hs = dout + OUT_HSTAB;
    const float* W1 = hW1 + (size_t)k * Hh * Hh;
    for (int b = 0; b < Bb; b++) {
        float acc = hb1[k * Hh + f];
        for (int i = 0; i < Hh; i++)
            acc = fmaf(hs[(size_t)b * (Kk * Hh) + k * Hh + i], W1[i * Hh + f], acc);
        hid[b][f] = fmaxf(acc, 0.f);
    }
    __syncthreads();
    int b = f >> 1, c = f & 1;
    const float* W2 = hW2 + (size_t)k * Hh * Cc;
    float acc = hb2[k * Cc + c];
    for (int i = 0; i < Hh; i++)
        acc = fmaf(hid[b][i], W2[i * Cc + c], acc);
    dout[OUT_LOGITS + (size_t)b * (Kk * Cc) + k * Cc + c] = acc;
}

// ---------------- launch ----------------
extern "C" void kernel_launch(void* const* d_in, const int* in_sizes, int n_in,
                              void* d_out, int out_size) {
    const float* x       = (const float*)d_in[0];
    const int*   ei      = (const int*)d_in[1];
    const int*   batch   = (const int*)d_in[2];
    const float* u       = (const float*)d_in[3];
    const float* enc_W1  = (const float*)d_in[4];
    const float* enc_b1  = (const float*)d_in[5];
    const float* enc_W2  = (const float*)d_in[6];
    const float* enc_b2  = (const float*)d_in[7];
    const float* enc_eps = (const float*)d_in[8];
    const float* cls_W1  = (const float*)d_in[9];
    const float* cls_b1  = (const float*)d_in[10];
    const float* cls_W2  = (const float*)d_in[11];
    const float* cls_b2  = (const float*)d_in[12];
    const float* cls_eps = (const float*)d_in[13];
    const float* mask_W1 = (const float*)d_in[14];
    const float* mask_b1 = (const float*)d_in[15];
    const float* mask_W2 = (const float*)d_in[16];
    const float* mask_b2 = (const float*)d_in[17];
    const float* head_W1 = (const float*)d_in[18];
    const float* head_b1 = (const float*)d_in[19];
    const float* head_W2 = (const float*)d_in[20];
    const float* head_b2 = (const float*)d_in[21];
    float* out = (float*)d_out;

    cudaFuncSetAttribute(mlp2_kernel, cudaFuncAttributeMaxDynamicSharedMemorySize, 163840);
    cudaFuncSetAttribute(gemm1_kernel, cudaFuncAttributeMaxDynamicSharedMemorySize, 98304);
    cudaFuncSetAttribute(mlp2_tc3, cudaFuncAttributeMaxDynamicSharedMemorySize, SMEM_TC3);

    float *ph0, *ph1, *pz, *peh0, *peh1, *pez;
    cudaGetSymbolAddress((void**)&ph0, g_h0);
    cudaGetSymbolAddress((void**)&ph1, g_h1);
    cudaGetSymbolAddress((void**)&pz, g_z);
    cudaGetSymbolAddress((void**)&peh0, g_eh0);
    cudaGetSymbolAddress((void**)&peh1, g_eh1);
    cudaGetSymbolAddress((void**)&pez, g_ez);

    // deterministic CSR + batch ranges
    zero_prep2<<<((size_t)NCH * Nn + 255) / 256, 256>>>();
    hist_chunk<<<(Ee + 255) / 256, 256>>>(ei);
    chunk_scan<<<(Nn + 255) / 256, 256>>>();
    scan_a<<<(Nn + 1023) / 1024, 1024>>>();
    scan_b<<<1, 32>>>((Nn + 1023) / 1024);
    scan_c<<<(Nn + 255) / 256, 256>>>();
    fill_det<<<NCH, 1024>>>(ei);
    bstart_kernel<<<(Nn + 255) / 256, 256>>>(batch);

    // expert weight pre-transpose (hi/lo tf32 split) into global scratch
    prep_wt<<<(Kk * Ll * 2 * 16384 + 255) / 256, 256>>>(cls_W1, cls_W2);

    // encoder GIN stack (exact fp32 — feeds the mask threshold path)
    const float* hin = x;
    float* hbuf[2] = { ph0, ph1 };
    for (int l = 0; l < Ll; l++) {
        agg_enc<<<(Nn * 32 + 255) / 256, 256>>>(hin, enc_eps + l);
        mlp2_kernel<<<dim3(313, 1, 1), 256, 163840>>>(
            pz, hbuf[l & 1],
            enc_W1 + (size_t)l * 16384, enc_b1 + l * 128,
            enc_W2 + (size_t)l * 16384, enc_b2 + l * 128,
            Nn);
        hin = hbuf[l & 1];
    }
    // Z = g_h0 (l=2 -> buf 0)

    // mask MLP layer-1 precompute: P = Z @ [Wtop|Wbot] per expert (+b1 on top)
    gemm1_kernel<<<dim3(313, 8), 256, 98304>>>(ph0, mask_W1, mask_b1, Nn);

    // per-edge mask logits + gumbel + masks
    edge_mask_kernel<<<Ee / 8, 256>>>(ei, u, mask_W2, mask_b2, out);
    nodemask_kernel<<<(Nn + 255) / 256, 256>>>(out);
    maskedx_kernel<<<(Kk * Nn * 32) / 256, 256>>>(x);

    // expert GIN stacks (3xTF32 tensor cores; ~fp32 accuracy)
    const float* ehin = peh0;
    float* ebuf[2] = { peh1, peh0 };
    for (int l = 0; l < Ll; l++) {
        agg_exp<<<dim3((Nn * 32 + 255) / 256, 1, Kk), 256>>>(ehin, cls_eps + l);
        mlp2_tc3<<<dim3(313, 1, Kk), 256, SMEM_TC3>>>(
            pez, ebuf[l & 1],
            cls_b1 + 0, cls_b2 + 0,
            l, Nn, Ll * 128);
        ehin = ebuf[l & 1];
    }
    // final expert h = g_eh1

    pool_kernel<<<dim3(Bb, Kk + 1), 512>>>(out);
    head_kernel<<<Kk, 128>>>(head_W1, head_b1, head_W2, head_b2, out);
}